// round 17
// baseline (speedup 1.0000x reference)
#include <cuda_runtime.h>
#include <cuda_bf16.h>
#include <math.h>

#define Bq 512
#define Nq 101
#define Hq 128
#define Tq 140
#define NP 104
#define VTS 27     // VT row stride in float4 units (108 floats): conflict-free

// __device__ scratch
__device__ float g_Wfw [129 * 128];                 // Wfc @ Ww
__device__ float g_Wpk2[128 * 128];                 // Wpk @ Wat^T   [k][o]
__device__ float g_pool [(size_t)Bq * Tq * 128];    // pool@Wfc1^(s+1)        [b][s][:]
__device__ float g_poolW[(size_t)Bq * Tq * 128];    // pool@Wfc1^(s+1)@Ww     [b][s][:]
__device__ float g_G[(size_t)Bq * Nq * 128];        // enc@Wfw[:128]          [b][n][:]

// monotone float<->u32 order-preserving map (for REDUX-based float max)
__device__ __forceinline__ unsigned f2mono(float f) {
    unsigned u = __float_as_uint(f);
    return (u & 0x80000000u) ? ~u : (u | 0x80000000u);
}
__device__ __forceinline__ float mono2f(unsigned k) {
    return __uint_as_float((k & 0x80000000u) ? (k & 0x7fffffffu) : ~k);
}

// packed f32x2 FMA: acc = a*b + acc (two independent IEEE fp32 FMAs)
#define FMA2(acc, a, b) \
    asm("fma.rn.f32x2 %0, %1, %2, %3;" : "=l"(acc) : "l"(a), "l"(b), "l"(acc))
__device__ __forceinline__ void unpk2(float& lo, float& hi, unsigned long long v) {
    unsigned a, bb;
    asm("mov.b64 {%0, %1}, %2;" : "=r"(a), "=r"(bb) : "l"(v));
    lo = __uint_as_float(a); hi = __uint_as_float(bb);
}

// ---------------------------------------------------------------------------
// P0: fold weights
// ---------------------------------------------------------------------------
__global__ void precomp0(const float* __restrict__ Wfc, const float* __restrict__ Ww,
                         const float* __restrict__ Wat, const float* __restrict__ Wpk) {
    __shared__ __align__(16) float row[128];
    const int t = threadIdx.x, bidx = blockIdx.x;
    if (bidx < 129) {
        row[t] = Wfc[bidx * 128 + t];
        __syncthreads();
        const float4* r4 = (const float4*)row;
        float a = 0.f;
        for (int k4 = 0; k4 < 32; k4++) {
            float4 r = r4[k4];
            a += r.x * Ww[(4 * k4 + 0) * 128 + t] + r.y * Ww[(4 * k4 + 1) * 128 + t]
               + r.z * Ww[(4 * k4 + 2) * 128 + t] + r.w * Ww[(4 * k4 + 3) * 128 + t];
        }
        g_Wfw[bidx * 128 + t] = a;
    } else {
        const int d = bidx - 129;
        row[t] = Wpk[d * 128 + t];
        __syncthreads();
        const float4* r4 = (const float4*)row;
        const float4* w4 = (const float4*)(Wat + t * 128);
        float a = 0.f;
        for (int k4 = 0; k4 < 32; k4++) {
            float4 r = r4[k4]; float4 wv = w4[k4];
            a += r.x * wv.x + r.y * wv.y + r.z * wv.z + r.w * wv.w;
        }
        g_Wpk2[d * 128 + t] = a;
    }
}

// ---------------------------------------------------------------------------
// P2a: pool chain ONLY. 2 batches/block.
// ---------------------------------------------------------------------------
__global__ __launch_bounds__(256)
void precomp2a(const float* __restrict__ pool, const float* __restrict__ Wfc1) {
    __shared__ __align__(16) float pA[128], pB[128];
    __shared__ float red2[256], red3[256];
    const int t = threadIdx.x, j = t & 127, kh = t >> 7;
    const int b0 = blockIdx.x * 2;
    float wf[64];
#pragma unroll
    for (int k = 0; k < 64; k++) wf[k] = Wfc1[(kh * 64 + k) * 128 + j];
    if (t < 128) { pA[t] = pool[b0 * 128 + t]; pB[t] = pool[(b0 + 1) * 128 + t]; }
    __syncthreads();
    for (int s = 0; s < Tq; s++) {
        const float4* pa4 = (const float4*)pA; const float4* pb4 = (const float4*)pB;
        float a0 = 0.f, a1 = 0.f;
#pragma unroll
        for (int k4 = 0; k4 < 16; k4++) {
            float4 xa = pa4[kh*16+k4], xb = pb4[kh*16+k4];
            a0 += xa.x*wf[4*k4] + xa.y*wf[4*k4+1] + xa.z*wf[4*k4+2] + xa.w*wf[4*k4+3];
            a1 += xb.x*wf[4*k4] + xb.y*wf[4*k4+1] + xb.z*wf[4*k4+2] + xb.w*wf[4*k4+3];
        }
        red2[t] = a0; red3[t] = a1;
        __syncthreads();
        if (t < 128) {
            float na = red2[t] + red2[t + 128];
            float nb = red3[t] + red3[t + 128];
            pA[t] = na; pB[t] = nb;
            g_pool[((size_t)b0 * Tq + s) * 128 + t]       = na;
            g_pool[((size_t)(b0 + 1) * Tq + s) * 128 + t] = nb;
        }
        __syncthreads();
    }
}

// ---------------------------------------------------------------------------
// P2b: g_poolW = g_pool @ Ww  (parallel GEMM, 16 rows/block)
// ---------------------------------------------------------------------------
__global__ __launch_bounds__(256)
void precomp2b(const float* __restrict__ Ww) {
    __shared__ __align__(16) float P[16 * 128];
    const int t = threadIdx.x;
    const size_t row0 = (size_t)blockIdx.x * 16;
    for (int i = t; i < 16 * 128; i += 256) P[i] = g_pool[row0 * 128 + i];
    __syncthreads();
    const int j = t & 127, half = t >> 7;
    float acc[8];
#pragma unroll
    for (int r = 0; r < 8; r++) acc[r] = 0.f;
    for (int d = 0; d < 128; d++) {
        float wv = Ww[d * 128 + j];
#pragma unroll
        for (int r = 0; r < 8; r++) acc[r] += P[(half * 8 + r) * 128 + d] * wv;
    }
#pragma unroll
    for (int r = 0; r < 8; r++)
        g_poolW[(row0 + half * 8 + r) * 128 + j] = acc[r];
}

// ---------------------------------------------------------------------------
// prologue matmul: 13-row chunk of one output column; E from global (bcast)
// ---------------------------------------------------------------------------
__device__ __forceinline__ void mm13(const float4* __restrict__ E4,
                                     const float* __restrict__ Wj,
                                     int n0, int cn, float* acc) {
#pragma unroll
    for (int r = 0; r < 13; r++) acc[r] = 0.f;
#pragma unroll 2
    for (int d4 = 0; d4 < 32; d4++) {
        float w0 = Wj[(4*d4+0)*128], w1 = Wj[(4*d4+1)*128];
        float w2 = Wj[(4*d4+2)*128], w3 = Wj[(4*d4+3)*128];
#pragma unroll
        for (int r = 0; r < 13; r++) if (r < cn) {
            float4 e = E4[(n0 + r) * 32 + d4];
            acc[r] = fmaf(e.x, w0, fmaf(e.y, w1, fmaf(e.z, w2, fmaf(e.w, w3, acc[r]))));
        }
    }
}

// ---------------------------------------------------------------------------
// Main decoder: 1 block / batch row, 256 threads, 2 CTAs/SM.
// f32x2 packed FMAs; V transposed (stride 108, conflict-free LDS.128).
// ---------------------------------------------------------------------------
__global__ __launch_bounds__(256, 2)
void decoder_main(const float* __restrict__ enc, const float* __restrict__ capc,
                  const float* __restrict__ demand, const float* __restrict__ Wk,
                  const float* __restrict__ Wv, float* __restrict__ out) {
    extern __shared__ __align__(16) float sm[];
    float* KT   = sm;                 // 128*104  K^T [d][n] (also Kp2 staging)
    float* VT   = sm + 13312;         // 128*108  V^T [o][m] padded
    float* comp = sm + 13312 + 13824; // 8*108 softmax exps / logit partials
    __shared__ __align__(16) float vAd[256];   // duplicated query/glimpse pairs
    __shared__ float logits[NP];
    __shared__ float lsep[2][8];

    const int t = threadIdx.x, b = blockIdx.x;
    const int j = t & 127;
    const int w = t >> 5, lane = t & 31;
    const unsigned FULL = 0xffffffffu;

    const float4* E4 = (const float4*)(enc + (size_t)b * Nq * 128);
    const int nbase = (t >> 7) ? 51 : 0;
    const int ncnt  = (t >> 7) ? 50 : 51;
    float acc[13];

    // ---- Phase Kp2: stage Kp2T[d][n] in KT, pick up to registers ----------
    for (int c0 = 0; c0 < ncnt; c0 += 13) {
        int cn = ncnt - c0; if (cn > 13) cn = 13;
        mm13(E4, g_Wpk2 + j, nbase + c0, cn, acc);
        for (int r = 0; r < cn; r++) KT[j * NP + (nbase + c0 + r)] = acc[r];
    }
    if (t < 128) { KT[t * NP + 101] = 0.f; KT[t * NP + 102] = 0.f; KT[t * NP + 103] = 0.f; }
    __syncthreads();
    unsigned long long kp2a[16], kp2b[16];   // packed pairs (n01),(n23) per row
    {
        const ulonglong2* K2 = (const ulonglong2*)KT;
        if (lane < 26) {
#pragma unroll
            for (int r = 0; r < 16; r++) {
                ulonglong2 kk = K2[(w * 16 + r) * 26 + lane];
                kp2a[r] = kk.x; kp2b[r] = kk.y;
            }
        } else {
#pragma unroll
            for (int r = 0; r < 16; r++) { kp2a[r] = 0ull; kp2b[r] = 0ull; }
        }
    }
    __syncthreads();

    // ---- Phase V: V^T[o][m] direct into padded VT -------------------------
    for (int c0 = 0; c0 < ncnt; c0 += 13) {
        int cn = ncnt - c0; if (cn > 13) cn = 13;
        mm13(E4, Wv + j, nbase + c0, cn, acc);
        for (int r = 0; r < cn; r++) VT[j * (VTS * 4) + (nbase + c0 + r)] = acc[r];
    }
    if (t < 128) {
        VT[t * (VTS*4) + 101] = 0.f; VT[t * (VTS*4) + 102] = 0.f;
        VT[t * (VTS*4) + 103] = 0.f;
        VT[t * (VTS*4) + 104] = 0.f; VT[t * (VTS*4) + 105] = 0.f;
        VT[t * (VTS*4) + 106] = 0.f; VT[t * (VTS*4) + 107] = 0.f;
    }

    // ---- Phase K: K^T[d][n] final resident in KT --------------------------
    for (int c0 = 0; c0 < ncnt; c0 += 13) {
        int cn = ncnt - c0; if (cn > 13) cn = 13;
        mm13(E4, Wk + j, nbase + c0, cn, acc);
        for (int r = 0; r < cn; r++) KT[j * NP + (nbase + c0 + r)] = acc[r];
    }
    if (t < 128) { KT[t * NP + 101] = 0.f; KT[t * NP + 102] = 0.f; KT[t * NP + 103] = 0.f; }

    // ---- Phase G: g_G[b][n][:] = E @ Wfw[:128] ----------------------------
    {
        float* gout = g_G + (size_t)b * Nq * 128;
        for (int c0 = 0; c0 < ncnt; c0 += 13) {
            int cn = ncnt - c0; if (cn > 13) cn = 13;
            mm13(E4, g_Wfw + j, nbase + c0, cn, acc);
            for (int r = 0; r < cn; r++) gout[(size_t)(nbase + c0 + r) * 128 + j] = acc[r];
        }
    }
    __syncthreads();   // all tiles + g_G ready

    // ---- warp-private register state --------------------------------------
    const float cap0 = capc[0];
    float dyn = capc[b];
    float dem4[4];
    unsigned m1b = 0;
#pragma unroll
    for (int k = 0; k < 4; k++) {
        int n = lane + 32 * k;
        dem4[k] = (n < Nq) ? demand[b * Nq + n] : 1e30f;
        if (n == 0 || n >= Nq) m1b |= (1u << k);
    }
    unsigned mw[4];
    {
        unsigned allm = 0xffffffffu;
#pragma unroll
        for (int k = 0; k < 4; k++) {
            int mk = ((m1b >> k) & 1) || (dem4[k] > dyn);
            mw[k] = __ballot_sync(FULL, mk);
            allm &= mw[k];
        }
        if (allm == 0xffffffffu) mw[0] &= ~1u;
    }
    int bi = 0, cnt = 0, pg = 1, par = 0;
    float logp = 0.f;

    const ulonglong2* KT2   = (const ulonglong2*)KT;
    const ulonglong2* VT2   = (const ulonglong2*)VT;
    const ulonglong2* comp2 = (const ulonglong2*)comp;
    const ulonglong2* vAd2  = (const ulonglong2*)vAd;
    float4* comp4 = (float4*)comp;
    const float* gG  = g_G + (size_t)b * Nq * 128;
    const float* gPW = g_poolW + (size_t)b * Tq * 128;

    const int oq = w * 16 + (lane & 15);
    const int ng = lane >> 4;
    const float wdyn = g_Wfw[128 * 128 + oq];
    float pw = gPW[oq];
    float qv = gG[oq];

    // =========================== step loop =================================
    for (int step = 0; step < Tq; step++) {
        // ---- Q slice (lanes 0-15 per warp), duplicated store --------------
        if (lane < 16) {
            float v = (qv + dyn * wdyn + pw) * 0.25f;
            ((float2*)vAd)[oq] = make_float2(v, v);
            int sn = step + 1; if (sn >= Tq) sn = Tq - 1;
            pw = gPW[(size_t)sn * 128 + oq];
        }
        __syncwarp();

        // ---- compat (f32x2) + masked softmax (in-warp, head w) ------------
        float ssum;
        {
            unsigned long long a01 = 0ull, a23 = 0ull;
            if (lane < 26) {
#pragma unroll
                for (int r2 = 0; r2 < 8; r2++) {
                    ulonglong2 qq = vAd2[w * 8 + r2];     // (q,q) pairs rows 2r2, 2r2+1
                    ulonglong2 k0 = KT2[(w * 16 + 2 * r2 + 0) * 26 + lane];
                    ulonglong2 k1 = KT2[(w * 16 + 2 * r2 + 1) * 26 + lane];
                    FMA2(a01, qq.x, k0.x); FMA2(a23, qq.x, k0.y);
                    FMA2(a01, qq.y, k1.x); FMA2(a23, qq.y, k1.y);
                }
            }
            float x0, x1, x2, x3;
            unpk2(x0, x1, a01); unpk2(x2, x3, a23);
            unsigned nib = (mw[lane >> 3] >> ((lane & 7) * 4)) & 0xFu;
            if (lane >= 26) nib = 0xFu;
            float v0 = (nib & 1u) ? -INFINITY : x0;
            float v1 = (nib & 2u) ? -INFINITY : x1;
            float v2 = (nib & 4u) ? -INFINITY : x2;
            float v3 = (nib & 8u) ? -INFINITY : x3;
            float mx = mono2f(__reduce_max_sync(FULL,
                        f2mono(fmaxf(fmaxf(v0, v1), fmaxf(v2, v3)))));
            float e0 = __expf(v0 - mx);
            float e1 = __expf(v1 - mx);
            float e2 = __expf(v2 - mx);
            float e3 = __expf(v3 - mx);
            if (lane < 26)
                comp4[w * 27 + lane] = make_float4(e0, e1, e2, e3);
            float s = (e0 + e1) + (e2 + e3);
#pragma unroll
            for (int o = 16; o; o >>= 1) s += __shfl_xor_sync(FULL, s, o);
            ssum = s;
        }
        __syncwarp();

        // ---- glimpse (f32x2): dims [16w,16w+16), V^T from smem ------------
        {
            unsigned long long g01 = 0ull, g23 = 0ull;
#pragma unroll
            for (int c = 0; c < 13; c++) {
                ulonglong2 vv = VT2[oq * VTS + ng * 13 + c];
                ulonglong2 ss = comp2[w * 27 + ng * 13 + c];
                FMA2(g01, ss.x, vv.x);
                FMA2(g23, ss.y, vv.y);
            }
            float ga, gb, gc, gd;
            unpk2(ga, gb, g01); unpk2(gc, gd, g23);
            float g = (ga + gb) + (gc + gd);
            g += __shfl_xor_sync(FULL, g, 16);
            if (lane < 16) {
                float v = __fdividef(g, ssum);
                ((float2*)vAd)[oq] = make_float2(v, v);
            }
        }
        __syncwarp();

        // ---- logits partial (f32x2, Kp2 in regs) -> comp row w ------------
        if (lane < 26) {
            unsigned long long a01 = 0ull, a23 = 0ull;
#pragma unroll
            for (int r2 = 0; r2 < 8; r2++) {
                ulonglong2 qq = vAd2[w * 8 + r2];
                FMA2(a01, qq.x, kp2a[2 * r2 + 0]); FMA2(a23, qq.x, kp2b[2 * r2 + 0]);
                FMA2(a01, qq.y, kp2a[2 * r2 + 1]); FMA2(a23, qq.y, kp2b[2 * r2 + 1]);
            }
            float x0, x1, x2, x3;
            unpk2(x0, x1, a01); unpk2(x2, x3, a23);
            comp4[w * 27 + lane] = make_float4(x0, x1, x2, x3);
        }
        __syncthreads();                                              // bar C

        // ---- warp w: logits slice n in [13w, 13w+13) ----------------------
        if (lane < 13) {
            const int n = 13 * w + lane;
            float s = comp[n];
#pragma unroll
            for (int k = 1; k < 8; k++) s += comp[k * 108 + n];
            float c2 = s * 0.08838834764831845f;
            int msk = (mw[n >> 5] >> (n & 31)) & 1;
            logits[n] = msk ? -INFINITY : 10.f * tanhf(c2);
        }
        __syncthreads();                                              // bar D

        // ---- argmax: local 4-slot max + REDUX value + min-index -----------
        float va0 = logits[lane];
        float va1 = logits[lane + 32];
        float va2 = logits[lane + 64];
        float va3 = (lane + 96 < NP) ? logits[lane + 96] : -INFINITY;
        float bl = va0; int bn = lane;
        if (va1 > bl) { bl = va1; bn = lane + 32; }
        if (va2 > bl) { bl = va2; bn = lane + 64; }
        if (va3 > bl) { bl = va3; bn = lane + 96; }
        float bv = mono2f(__reduce_max_sync(FULL, f2mono(bl)));
        unsigned cand = (bl == bv) ? (unsigned)bn : 0xFFFFu;
        bi = (int)__reduce_min_sync(FULL, cand);

        // ---- early G load for next step -----------------------------------
        if (lane < 16) qv = gG[(size_t)bi * 128 + oq];

        // ---- warp0: fold previous step's lse partials ---------------------
        if (w == 0 && lane == 0 && step > 0 && pg) {
            float ss = lsep[par ^ 1][0] + lsep[par ^ 1][1] + lsep[par ^ 1][2]
                     + lsep[par ^ 1][3] + lsep[par ^ 1][4] + lsep[par ^ 1][5]
                     + lsep[par ^ 1][6] + lsep[par ^ 1][7];
            logp -= logf(ss);
        }
        if (w == 0 && lane == 0) out[b * Tq + step] = (float)bi;

        // ---- state update (warp-private registers) ------------------------
        {
            const int ks = bi >> 5, ls = bi & 31;
            float dv = __shfl_sync(FULL, dem4[ks], ls);
            unsigned m1o = __shfl_sync(FULL, m1b, ls);
            int was = (m1o >> ks) & 1;
            pg = (cnt < Nq - 1);
            if (bi > 0 && !was) cnt++;
            if (bi > 0 && lane == ls) m1b |= (1u << ks);
            if (lane == 0) m1b = (m1b & ~1u) | (bi == 0 ? 1u : 0u);
            dyn = (bi == 0) ? cap0 : (dyn - dv);
            unsigned allm = 0xffffffffu;
#pragma unroll
            for (int k = 0; k < 4; k++) {
                int mk = ((m1b >> k) & 1) || (dem4[k] > dyn);
                mw[k] = __ballot_sync(FULL, mk);
                allm &= mw[k];
            }
            if (allm == 0xffffffffu) mw[0] &= ~1u;
        }

        // ---- lse partial for this step (slice [13w,13w+13)) ---------------
        {
            float e = 0.f;
            if (lane < 13) e = __expf(logits[13 * w + lane] - bv);
#pragma unroll
            for (int o = 8; o; o >>= 1) e += __shfl_xor_sync(FULL, e, o);
            if (lane == 0) lsep[par][w] = e;
        }
        par ^= 1;
    }

    __syncthreads();
    if (w == 0 && lane == 0) {
        if (pg) {
            float ss = lsep[par ^ 1][0] + lsep[par ^ 1][1] + lsep[par ^ 1][2]
                     + lsep[par ^ 1][3] + lsep[par ^ 1][4] + lsep[par ^ 1][5]
                     + lsep[par ^ 1][6] + lsep[par ^ 1][7];
            logp -= logf(ss);
        }
        out[Bq * Tq + b] = logp;
    }
}

// ---------------------------------------------------------------------------
extern "C" void kernel_launch(void* const* d_in, const int* in_sizes, int n_in,
                              void* d_out, int out_size) {
    const float *enc = nullptr, *pool = nullptr, *capc = nullptr, *dem = nullptr, *Wfc = nullptr;
    const float* w16[8] = {nullptr};
    int nw = 0;
    for (int i = 0; i < n_in; i++) {
        int s = in_sizes[i];
        if      (s == Bq * Nq * 128) enc  = (const float*)d_in[i];
        else if (s == Bq * Hq)       pool = (const float*)d_in[i];
        else if (s == Bq)            capc = (const float*)d_in[i];
        else if (s == Bq * Nq)       dem  = (const float*)d_in[i];
        else if (s == (Hq + 1) * Hq) Wfc  = (const float*)d_in[i];
        else if (s == Hq * Hq) { if (nw < 8) w16[nw++] = (const float*)d_in[i]; }
    }
    // dict order among 128x128: W_fc1, W_w, W_k, W_v, W_attnfc, W_pk
    const float* Wfc1 = w16[0];
    const float* Ww   = w16[1];
    const float* Wk   = w16[2];
    const float* Wv   = w16[3];
    const float* Wat  = w16[4];
    const float* Wpk  = w16[5];

    const int smem_main = (13312 + 13824 + 864) * (int)sizeof(float);  // 112000 B
    cudaFuncSetAttribute(decoder_main, cudaFuncAttributeMaxDynamicSharedMemorySize, smem_main);

    precomp0<<<257, 128>>>(Wfc, Ww, Wat, Wpk);
    precomp2a<<<Bq / 2, 256>>>(pool, Wfc1);
    precomp2b<<<(Bq * Tq) / 16, 256>>>(Ww);
    decoder_main<<<Bq, 256, smem_main>>>(enc, capc, dem, Wk, Wv, (float*)d_out);
}